// round 17
// baseline (speedup 1.0000x reference)
#include <cuda_runtime.h>
#include <cuda_bf16.h>
#include <math_constants.h>

#define B_ 8
#define T_ 2048
#define C_ 1024
#define H_ 64
#define M_ (B_*T_)

// Packed bf16 hi/lo pairs (u32 = two bf16 along the mma k-dim).
// qs = qr+qi, kd = kr-ki (for attention-side Karatsuba).
__device__ unsigned g_qrh[M_*32], g_qrl[M_*32], g_qih[M_*32], g_qil[M_*32];
__device__ unsigned g_qsh[M_*32], g_qsl[M_*32];
__device__ unsigned g_krh[M_*32], g_krl[M_*32], g_kih[M_*32], g_kil[M_*32];
__device__ unsigned g_kdh[M_*32], g_kdl[M_*32];
__device__ unsigned g_vrh[(size_t)H_*(M_/2)], g_vrl[(size_t)H_*(M_/2)];
__device__ unsigned g_vih[(size_t)H_*(M_/2)], g_vil[(size_t)H_*(M_/2)];

__device__ __forceinline__ unsigned pkbf2(float lo, float hi) {
    unsigned r; asm("cvt.rn.bf16x2.f32 %0, %1, %2;" : "=r"(r) : "f"(hi), "f"(lo));
    return r;
}
__device__ __forceinline__ void split1(float x, float& h, float& l) {
    h = __bfloat162float(__float2bfloat16(x));
    l = x - h;
}
__device__ __forceinline__ void mma16(float* d, const unsigned* a, const unsigned* b) {
    asm volatile("mma.sync.aligned.m16n8k16.row.col.f32.bf16.bf16.f32 "
        "{%0,%1,%2,%3}, {%4,%5,%6,%7}, {%8,%9}, {%0,%1,%2,%3};"
        : "+f"(d[0]), "+f"(d[1]), "+f"(d[2]), "+f"(d[3])
        : "r"(a[0]), "r"(a[1]), "r"(a[2]), "r"(a[3]), "r"(b[0]), "r"(b[1]));
}
__device__ __forceinline__ unsigned smem_u32(const void* p) {
    unsigned a;
    asm("{ .reg .u64 t; cvta.to.shared.u64 t, %1; cvt.u32.u64 %0, t; }"
        : "=r"(a) : "l"(p));
    return a;
}
__device__ __forceinline__ void cpa16(unsigned saddr, const void* g) {
    asm volatile("cp.async.cg.shared.global [%0], [%1], 16;"
                 :: "r"(saddr), "l"(g) : "memory");
}
__device__ __forceinline__ void ldsm4(unsigned* r, unsigned addr) {
    asm volatile("ldmatrix.sync.aligned.m8n8.x4.shared.b16 {%0,%1,%2,%3}, [%4];"
        : "=r"(r[0]), "=r"(r[1]), "=r"(r[2]), "=r"(r[3]) : "r"(addr));
}
#define CP_COMMIT() asm volatile("cp.async.commit_group;" ::: "memory")
#define CP_WAIT2()  asm volatile("cp.async.wait_group 2;" ::: "memory")
#define CP_WAIT1()  asm volatile("cp.async.wait_group 1;" ::: "memory")
#define CP_WAIT0()  asm volatile("cp.async.wait_group 0;" ::: "memory")

// ===========================================================================
// Projection via Karatsuba (unchanged core from R16); epilogue additionally
// emits qs = qr+qi (for Q) and kd = kr-ki (for K), pre-split.
// ===========================================================================
#define PJA_XRH 0
#define PJA_XRL 2560
#define PJA_XIH 5120
#define PJA_XIL 7680
#define PJA_XSH 10240
#define PJA_XSL 12800
#define PJB_WRH 15360
#define PJB_WIH 17920
#define PJB_WSH 20480
#define PJ_U32  23040

__global__ __launch_bounds__(512, 1) void proj_kernel(
    const float* __restrict__ xr,  const float* __restrict__ xi,
    const float* __restrict__ Wkr, const float* __restrict__ Wki,
    const float* __restrict__ Wqr, const float* __restrict__ Wqi,
    const float* __restrict__ Wvr, const float* __restrict__ Wvi)
{
    extern __shared__ unsigned smu[];
    const unsigned sbase = smem_u32(smu);

    const int tid  = threadIdx.x;
    const int lane = tid & 31;
    const int w    = tid >> 5;
    const int wm   = w >> 2;
    const int wn   = w & 3;
    const int g    = lane >> 2;
    const int kl   = lane & 3;

    const int rt  = blockIdx.x / 3;
    const int mat = blockIdx.x % 3;   // 0=K 1=Q 2=V
    const int m0  = rt * 128;

    const float* Wr_ = (mat==0)? Wkr : (mat==1)? Wqr : Wvr;
    const float* Wi_ = (mat==0)? Wki : (mat==1)? Wqi : Wvi;

    float T1[2][2][4], T2[2][2][4], T3[2][2][4];
    #pragma unroll
    for (int mt=0; mt<2; ++mt)
        #pragma unroll
        for (int nt=0; nt<2; ++nt)
            #pragma unroll
            for (int r=0; r<4; ++r) { T1[mt][nt][r]=0.f; T2[mt][nt][r]=0.f; T3[mt][nt][r]=0.f; }

    const int a_row = tid >> 2;
    const int a_q8  = (tid & 3) * 8;
    const float* ar_src = xr + (size_t)(m0 + a_row)*C_ + a_q8;
    const float* ai_src = xi + (size_t)(m0 + a_row)*C_ + a_q8;
    const int b_n  = tid & 63;
    const int b_kq = tid >> 6;

    const unsigned a_base = (unsigned)((wm*32 + (((lane>>3)&1)<<3) + (lane&7))*20
                                       + ((lane>>4)<<2));
    const unsigned b_base = (unsigned)(((lane>>4) ? 1280 : 0)
                                       + (wn*16 + (lane&7))*20 + (((lane>>3)&1)<<2));

    for (int c0 = 0; c0 < C_; c0 += 32) {
        __syncthreads();
        {
            float4 r0 = *(const float4*)(ar_src + c0);
            float4 r1 = *(const float4*)(ar_src + c0 + 4);
            float4 i0 = *(const float4*)(ai_src + c0);
            float4 i1 = *(const float4*)(ai_src + c0 + 4);
            float a[8] = {r0.x,r0.y,r0.z,r0.w,r1.x,r1.y,r1.z,r1.w};
            float b[8] = {i0.x,i0.y,i0.z,i0.w,i1.x,i1.y,i1.z,i1.w};
            float h[8], l[8];
            const int ao = a_row*20 + (a_q8 >> 1);
            #pragma unroll
            for (int j=0;j<8;++j) split1(a[j],h[j],l[j]);
            *(uint4*)&smu[PJA_XRH + ao] = make_uint4(pkbf2(h[0],h[1]),pkbf2(h[2],h[3]),pkbf2(h[4],h[5]),pkbf2(h[6],h[7]));
            *(uint4*)&smu[PJA_XRL + ao] = make_uint4(pkbf2(l[0],l[1]),pkbf2(l[2],l[3]),pkbf2(l[4],l[5]),pkbf2(l[6],l[7]));
            #pragma unroll
            for (int j=0;j<8;++j) split1(b[j],h[j],l[j]);
            *(uint4*)&smu[PJA_XIH + ao] = make_uint4(pkbf2(h[0],h[1]),pkbf2(h[2],h[3]),pkbf2(h[4],h[5]),pkbf2(h[6],h[7]));
            *(uint4*)&smu[PJA_XIL + ao] = make_uint4(pkbf2(l[0],l[1]),pkbf2(l[2],l[3]),pkbf2(l[4],l[5]),pkbf2(l[6],l[7]));
            #pragma unroll
            for (int j=0;j<8;++j) split1(a[j]+b[j],h[j],l[j]);
            *(uint4*)&smu[PJA_XSH + ao] = make_uint4(pkbf2(h[0],h[1]),pkbf2(h[2],h[3]),pkbf2(h[4],h[5]),pkbf2(h[6],h[7]));
            *(uint4*)&smu[PJA_XSL + ao] = make_uint4(pkbf2(l[0],l[1]),pkbf2(l[2],l[3]),pkbf2(l[4],l[5]),pkbf2(l[6],l[7]));
        }
        {
            #pragma unroll
            for (int j = 0; j < 2; ++j) {
                const int p = b_kq*2 + j;
                const size_t krow = (size_t)(c0 + 2*p);
                const float wr0 = Wr_[krow*H_ + b_n], wr1 = Wr_[krow*H_ + H_ + b_n];
                const float wi0 = Wi_[krow*H_ + b_n], wi1 = Wi_[krow*H_ + H_ + b_n];
                float h0,l0,h1,l1;
                split1(wr0,h0,l0); split1(wr1,h1,l1);
                smu[PJB_WRH +        b_n*20 + p] = pkbf2(h0,h1);
                smu[PJB_WRH + 1280 + b_n*20 + p] = pkbf2(l0,l1);
                split1(wi0,h0,l0); split1(wi1,h1,l1);
                smu[PJB_WIH +        b_n*20 + p] = pkbf2(h0,h1);
                smu[PJB_WIH + 1280 + b_n*20 + p] = pkbf2(l0,l1);
                split1(wr0+wi0,h0,l0); split1(wr1+wi1,h1,l1);
                smu[PJB_WSH +        b_n*20 + p] = pkbf2(h0,h1);
                smu[PJB_WSH + 1280 + b_n*20 + p] = pkbf2(l0,l1);
            }
        }
        __syncthreads();

        #pragma unroll
        for (int ks = 0; ks < 2; ++ks) {
            const unsigned pb = ks*8;
            #pragma unroll
            for (int mt = 0; mt < 2; ++mt) {
                const unsigned ao = a_base + mt*320 + pb;
                unsigned xrh_[4], xrl_[4], xih_[4], xil_[4], xsh_[4], xsl_[4];
                ldsm4(xrh_, sbase + (PJA_XRH + ao)*4u);
                ldsm4(xrl_, sbase + (PJA_XRL + ao)*4u);
                ldsm4(xih_, sbase + (PJA_XIH + ao)*4u);
                ldsm4(xil_, sbase + (PJA_XIL + ao)*4u);
                ldsm4(xsh_, sbase + (PJA_XSH + ao)*4u);
                ldsm4(xsl_, sbase + (PJA_XSL + ao)*4u);
                #pragma unroll
                for (int nt = 0; nt < 2; ++nt) {
                    const unsigned bo = b_base + nt*160 + pb;
                    unsigned wr_[4], wi_[4], ws_[4];
                    ldsm4(wr_, sbase + (PJB_WRH + bo)*4u);
                    ldsm4(wi_, sbase + (PJB_WIH + bo)*4u);
                    ldsm4(ws_, sbase + (PJB_WSH + bo)*4u);
                    mma16(T1[mt][nt], xrh_, wr_);
                    mma16(T1[mt][nt], xrh_, wr_+2);
                    mma16(T1[mt][nt], xrl_, wr_);
                    mma16(T2[mt][nt], xih_, wi_);
                    mma16(T2[mt][nt], xih_, wi_+2);
                    mma16(T2[mt][nt], xil_, wi_);
                    mma16(T3[mt][nt], xsh_, ws_);
                    mma16(T3[mt][nt], xsh_, ws_+2);
                    mma16(T3[mt][nt], xsl_, ws_);
                }
            }
        }
    }

    // ---- epilogue ----
    if (mat != 2) {
        const int isK = (mat == 0);
        unsigned *QRh = isK ? g_krh : g_qrh, *QRl = isK ? g_krl : g_qrl;
        unsigned *QIh = isK ? g_kih : g_qih, *QIl = isK ? g_kil : g_qil;
        unsigned *QXh = isK ? g_kdh : g_qsh, *QXl = isK ? g_kdl : g_qsl;
        #pragma unroll
        for (int mt = 0; mt < 2; ++mt) {
            const int rA = m0 + wm*32 + mt*16 + g;
            const int rB = rA + 8;
            #pragma unroll
            for (int nt = 0; nt < 2; ++nt) {
                const int pidx = wn*8 + nt*4 + kl;
                float r_[4], i_[4], x_[4];
                #pragma unroll
                for (int r=0;r<4;++r) {
                    r_[r] = T1[mt][nt][r] - T2[mt][nt][r];
                    i_[r] = T3[mt][nt][r] - T1[mt][nt][r] - T2[mt][nt][r];
                    x_[r] = isK ? (r_[r] - i_[r]) : (r_[r] + i_[r]);
                }
                float h0,l0,h1,l1;
                split1(r_[0],h0,l0); split1(r_[1],h1,l1);
                QRh[(size_t)rA*32 + pidx] = pkbf2(h0,h1);
                QRl[(size_t)rA*32 + pidx] = pkbf2(l0,l1);
                split1(r_[2],h0,l0); split1(r_[3],h1,l1);
                QRh[(size_t)rB*32 + pidx] = pkbf2(h0,h1);
                QRl[(size_t)rB*32 + pidx] = pkbf2(l0,l1);
                split1(i_[0],h0,l0); split1(i_[1],h1,l1);
                QIh[(size_t)rA*32 + pidx] = pkbf2(h0,h1);
                QIl[(size_t)rA*32 + pidx] = pkbf2(l0,l1);
                split1(i_[2],h0,l0); split1(i_[3],h1,l1);
                QIh[(size_t)rB*32 + pidx] = pkbf2(h0,h1);
                QIl[(size_t)rB*32 + pidx] = pkbf2(l0,l1);
                split1(x_[0],h0,l0); split1(x_[1],h1,l1);
                QXh[(size_t)rA*32 + pidx] = pkbf2(h0,h1);
                QXl[(size_t)rA*32 + pidx] = pkbf2(l0,l1);
                split1(x_[2],h0,l0); split1(x_[3],h1,l1);
                QXh[(size_t)rB*32 + pidx] = pkbf2(h0,h1);
                QXl[(size_t)rB*32 + pidx] = pkbf2(l0,l1);
            }
        }
    } else {
        #pragma unroll
        for (int mt = 0; mt < 2; ++mt) {
            const int rA = m0 + wm*32 + mt*16 + g;
            const int rB = rA + 8;
            #pragma unroll
            for (int nt = 0; nt < 2; ++nt) {
                const int c0c = wn*16 + nt*8 + 2*kl;
                float r_[4], i_[4];
                #pragma unroll
                for (int r=0;r<4;++r) {
                    r_[r] = T1[mt][nt][r] - T2[mt][nt][r];
                    i_[r] = T3[mt][nt][r] - T1[mt][nt][r] - T2[mt][nt][r];
                }
                float pr[4], pi[4];
                #pragma unroll
                for (int r=0;r<4;++r) {
                    pr[r] = __shfl_xor_sync(~0u, r_[r], 4);
                    pi[r] = __shfl_xor_sync(~0u, i_[r], 4);
                }
                if ((g & 1) == 0) {
                    const size_t pA = (size_t)(rA >> 1);
                    const size_t pB = (size_t)(rB >> 1);
                    float h0,l0,h1,l1;
                    split1(r_[0],h0,l0); split1(pr[0],h1,l1);
                    g_vrh[(size_t)c0c*(M_/2) + pA] = pkbf2(h0,h1);
                    g_vrl[(size_t)c0c*(M_/2) + pA] = pkbf2(l0,l1);
                    split1(r_[1],h0,l0); split1(pr[1],h1,l1);
                    g_vrh[(size_t)(c0c+1)*(M_/2) + pA] = pkbf2(h0,h1);
                    g_vrl[(size_t)(c0c+1)*(M_/2) + pA] = pkbf2(l0,l1);
                    split1(r_[2],h0,l0); split1(pr[2],h1,l1);
                    g_vrh[(size_t)c0c*(M_/2) + pB] = pkbf2(h0,h1);
                    g_vrl[(size_t)c0c*(M_/2) + pB] = pkbf2(l0,l1);
                    split1(r_[3],h0,l0); split1(pr[3],h1,l1);
                    g_vrh[(size_t)(c0c+1)*(M_/2) + pB] = pkbf2(h0,h1);
                    g_vrl[(size_t)(c0c+1)*(M_/2) + pB] = pkbf2(l0,l1);
                    split1(i_[0],h0,l0); split1(pi[0],h1,l1);
                    g_vih[(size_t)c0c*(M_/2) + pA] = pkbf2(h0,h1);
                    g_vil[(size_t)c0c*(M_/2) + pA] = pkbf2(l0,l1);
                    split1(i_[1],h0,l0); split1(pi[1],h1,l1);
                    g_vih[(size_t)(c0c+1)*(M_/2) + pA] = pkbf2(h0,h1);
                    g_vil[(size_t)(c0c+1)*(M_/2) + pA] = pkbf2(l0,l1);
                    split1(i_[2],h0,l0); split1(pi[2],h1,l1);
                    g_vih[(size_t)c0c*(M_/2) + pB] = pkbf2(h0,h1);
                    g_vil[(size_t)c0c*(M_/2) + pB] = pkbf2(l0,l1);
                    split1(i_[3],h0,l0); split1(pi[3],h1,l1);
                    g_vih[(size_t)(c0c+1)*(M_/2) + pB] = pkbf2(h0,h1);
                    g_vil[(size_t)(c0c+1)*(M_/2) + pB] = pkbf2(l0,l1);
                }
            }
        }
    }
}

// ===========================================================================
// Flash attention: causal-paired, plain-exp, ldmatrix, QK Karatsuba
// (T1=qr@kr, T2=qi@ki, T3=qs@kd; Sr=T1+T2, Si=T3-T1+T2).
// K double-buffered (6 arrays), V single-buffered (hidden behind scores).
// ===========================================================================
#define AQ_  0                    // QRH 0, QRL 2304, QIH 4608, QIL 6912, QSH 9216, QSL 11520
#define APH 13824
#define APL 16128
#define AK_ 18432                 // per stage: KRH 0, KIH 2304, KRL 4608, KIL 6912, KDH 9216, KDL 11520
#define K_STAGE 13824
#define AV_ 46080                 // VRH 0, VIH 2304, VRL 4608, VIL 6912
#define AT_U32 55296
#define AT_BYTES ((AT_U32 + 256)*4)

__global__ __launch_bounds__(512, 1) void attn_kernel(float* __restrict__ out)
{
    extern __shared__ unsigned smu[];
    float* reds = (float*)(smu + AT_U32);
    const unsigned sbase = smem_u32(smu);

    const int b    = blockIdx.y;
    const int pp   = blockIdx.x;
    const int tid  = threadIdx.x;
    const int lane = tid & 31;
    const int w    = tid >> 5;
    const int wm   = w >> 2;
    const int wn   = w & 3;
    const int g    = lane >> 2;
    const int kl   = lane & 3;
    const int lr0 = wm*16 + g, lr1 = lr0 + 8;

    const int sm_row = tid >> 3;
    const int sm_qq  = (tid & 7)*4;

    const unsigned a_off  = (unsigned)((wm*16 + (((lane>>3)&1)<<3) + (lane&7))*36
                                       + ((lane>>4)<<2));
    const unsigned b_off  = (unsigned)(((lane>>4) ? 4608 : 0)
                                       + (lane&7)*36 + (((lane>>3)&1)<<2));
    const unsigned b_off2 = (unsigned)(((lane>>4) ? 2304 : 0)
                                       + (lane&7)*36 + (((lane>>3)&1)<<2));

    #pragma unroll 1
    for (int pass = 0; pass < 2; ++pass) {
        const int qt = pass ? pp : (31 - pp);
        const int qbase = b*T_ + qt*64;

        {   // prologue: prefetch K tile 0 into stage 0 (group)
            const int kb_row = b*T_;
            const unsigned so = sbase + (unsigned)(AK_ + sm_row*36 + sm_qq)*4u;
            const size_t kb = (size_t)(kb_row + sm_row)*32 + sm_qq;
            cpa16(so + 0*2304*4, &g_krh[kb]);
            cpa16(so + 1*2304*4, &g_kih[kb]);
            cpa16(so + 2*2304*4, &g_krl[kb]);
            cpa16(so + 3*2304*4, &g_kil[kb]);
            cpa16(so + 4*2304*4, &g_kdh[kb]);
            cpa16(so + 5*2304*4, &g_kdl[kb]);
            CP_COMMIT();
        }
        {   // stage Q (6 arrays)
            const size_t base = (size_t)(qbase + sm_row)*32 + sm_qq;
            *(uint4*)&smu[AQ_ +     0 + sm_row*36 + sm_qq] = *(const uint4*)&g_qrh[base];
            *(uint4*)&smu[AQ_ +  2304 + sm_row*36 + sm_qq] = *(const uint4*)&g_qrl[base];
            *(uint4*)&smu[AQ_ +  4608 + sm_row*36 + sm_qq] = *(const uint4*)&g_qih[base];
            *(uint4*)&smu[AQ_ +  6912 + sm_row*36 + sm_qq] = *(const uint4*)&g_qil[base];
            *(uint4*)&smu[AQ_ +  9216 + sm_row*36 + sm_qq] = *(const uint4*)&g_qsh[base];
            *(uint4*)&smu[AQ_ + 11520 + sm_row*36 + sm_qq] = *(const uint4*)&g_qsl[base];
        }

        float Or[2][4], Oi[2][4];
        float rs0 = 0.f, rs1 = 0.f;
        #pragma unroll
        for (int nt=0;nt<2;nt++)
            #pragma unroll
            for (int r=0;r<4;r++) { Or[nt][r]=0.f; Oi[nt][r]=0.f; }

        for (int kt = 0; kt <= qt; ++kt) {
            const int cur = kt & 1;
            __syncthreads();   // prior step reads of V buf / P / K[1-cur] done
            {   // issue V for THIS step (single buffer; hidden behind scores)
                const int kb_row = b*T_ + kt*64;
                const unsigned so = sbase + (unsigned)(AV_ + sm_row*36 + sm_qq)*4u;
                const size_t vb = (size_t)sm_row*(M_/2) + (size_t)(kb_row >> 1) + sm_qq;
                cpa16(so + 0*2304*4, &g_vrh[vb]);
                cpa16(so + 1*2304*4, &g_vih[vb]);
                cpa16(so + 2*2304*4, &g_vrl[vb]);
                cpa16(so + 3*2304*4, &g_vil[vb]);
                CP_COMMIT();
            }
            if (kt < qt) {   // issue K for NEXT step into other stage
                const int kb_row = b*T_ + (kt+1)*64;
                const unsigned so = sbase
                    + (unsigned)(AK_ + (1-cur)*K_STAGE + sm_row*36 + sm_qq)*4u;
                const size_t kb = (size_t)(kb_row + sm_row)*32 + sm_qq;
                cpa16(so + 0*2304*4, &g_krh[kb]);
                cpa16(so + 1*2304*4, &g_kih[kb]);
                cpa16(so + 2*2304*4, &g_krl[kb]);
                cpa16(so + 3*2304*4, &g_kil[kb]);
                cpa16(so + 4*2304*4, &g_kdh[kb]);
                cpa16(so + 5*2304*4, &g_kdl[kb]);
                CP_COMMIT();
                CP_WAIT2();     // all but {K_next, V_cur} done -> K_cur ready
            } else {
                CP_WAIT1();     // only V_cur outstanding -> K_cur ready
            }
            __syncthreads();

            const unsigned KH = AK_ + cur*K_STAGE;

            // ---- scores: T1=qr@kr, T2=qi@ki, T3=qs@kd ----
            float t1[2][4], t2[2][4], t3[2][4];
            #pragma unroll
            for (int nt=0;nt<2;nt++)
                #pragma unroll
                for (int r=0;r<4;r++) { t1[nt][r]=0.f; t2[nt][r]=0.f; t3[nt][r]=0.f; }

            #pragma unroll
            for (int ks = 0; ks < 4; ++ks) {
                const unsigned pb = ks*8;
                unsigned qr_[4], ql_[4], qi_[4], qj_[4], qs_[4], qt_[4];
                ldsm4(qr_, sbase + (AQ_ +     0 + a_off + pb)*4u);
                ldsm4(ql_, sbase + (AQ_ +  2304 + a_off + pb)*4u);
                ldsm4(qi_, sbase + (AQ_ +  4608 + a_off + pb)*4u);
                ldsm4(qj_, sbase + (AQ_ +  6912 + a_off + pb)*4u);
                ldsm4(qs_, sbase + (AQ_ +  9216 + a_off + pb)*4u);
                ldsm4(qt_, sbase + (AQ_ + 11520 + a_off + pb)*4u);
                #pragma unroll
                for (int nt = 0; nt < 2; ++nt) {
                    const unsigned n0b = (unsigned)((wn*16 + nt*8)*36);
                    unsigned kr_[4], ki_[4], kd_[4];
                    ldsm4(kr_, sbase + (KH +        n0b + b_off  + pb)*4u);
                    ldsm4(ki_, sbase + (KH + 2304 + n0b + b_off  + pb)*4u);
                    ldsm4(kd_, sbase + (KH + 9216 + n0b + b_off2 + pb)*4u);
                    mma16(t1[nt], qr_, kr_);
                    mma16(t1[nt], qr_, kr_+2);
                    mma16(t1[nt], ql_, kr_);
                    mma16(t2[nt], qi_, ki_);
                    mma16(t2[nt], qi_, ki_+2);
                    mma16(t2[nt], qj_, ki_);
                    mma16(t3[nt], qs_, kd_);
                    mma16(t3[nt], qs_, kd_+2);
                    mma16(t3[nt], qt_, kd_);
                }
            }

            // ---- combine + magnitude + mask + exp + P store ----
            #pragma unroll
            for (int nt = 0; nt < 2; ++nt) {
                float e[4];
                #pragma unroll
                for (int r = 0; r < 4; ++r) {
                    const float sr = t1[nt][r] + t2[nt][r];
                    const float si = t3[nt][r] - t1[nt][r] + t2[nt][r];
                    const float m2 = fmaf(sr, sr, fmaf(si, si, 1e-4f));
                    const float v = m2 * rsqrtf(m2) * 0.125f;
                    const int colg = kt*64 + wn*16 + nt*8 + 2*kl + (r&1);
                    const int rowg = qt*64 + ((r<2) ? lr0 : lr1);
                    e[r] = (colg <= rowg) ? __expf(v) : 0.f;
                }
                rs0 += e[0] + e[1];
                rs1 += e[2] + e[3];
                const int pidx = wn*8 + nt*4 + kl;
                float h0,l0,h1,l1,h2,l2,h3,l3;
                split1(e[0],h0,l0); split1(e[1],h1,l1);
                split1(e[2],h2,l2); split1(e[3],h3,l3);
                smu[APH + lr0*36 + pidx] = pkbf2(h0,h1);
                smu[APL + lr0*36 + pidx] = pkbf2(l0,l1);
                smu[APH + lr1*36 + pidx] = pkbf2(h2,h3);
                smu[APL + lr1*36 + pidx] = pkbf2(l2,l3);
            }
            if (kt < qt) CP_WAIT1(); else CP_WAIT0();   // V_cur ready
            __syncthreads();

            // ---- O += P @ V ----
            #pragma unroll
            for (int ks = 0; ks < 4; ++ks) {
                const unsigned pb = ks*8;
                unsigned ph_[4], pl_[4];
                ldsm4(ph_, sbase + (APH + a_off + pb)*4u);
                ldsm4(pl_, sbase + (APL + a_off + pb)*4u);
                #pragma unroll
                for (int nt = 0; nt < 2; ++nt) {
                    const unsigned n0b = (unsigned)((wn*16 + nt*8)*36);
                    unsigned vr_[4], vi_[4];
                    ldsm4(vr_, sbase + (AV_ +        n0b + b_off + pb)*4u);
                    ldsm4(vi_, sbase + (AV_ + 2304 + n0b + b_off + pb)*4u);
                    mma16(Or[nt], ph_, vr_);
                    mma16(Or[nt], ph_, vr_+2);
                    mma16(Or[nt], pl_, vr_);
                    mma16(Oi[nt], ph_, vi_);
                    mma16(Oi[nt], ph_, vi_+2);
                    mma16(Oi[nt], pl_, vi_);
                }
            }
        }

        rs0 += __shfl_xor_sync(~0u, rs0, 1);
        rs0 += __shfl_xor_sync(~0u, rs0, 2);
        rs1 += __shfl_xor_sync(~0u, rs1, 1);
        rs1 += __shfl_xor_sync(~0u, rs1, 2);
        __syncthreads();
        if (kl == 0) { reds[wn*64 + lr0] = rs0; reds[wn*64 + lr1] = rs1; }
        __syncthreads();

        const float inv0 = 1.f / (reds[lr0] + reds[64+lr0] + reds[128+lr0] + reds[192+lr0]);
        const float inv1 = 1.f / (reds[lr1] + reds[64+lr1] + reds[128+lr1] + reds[192+lr1]);
        #pragma unroll
        for (int nt = 0; nt < 2; ++nt) {
            const int h0 = wn*16 + nt*8 + 2*kl;
            const size_t rA = (size_t)(qbase + lr0);
            const size_t rB = (size_t)(qbase + lr1);
            *(float2*)(out + rA*H_ + h0) = make_float2(Or[nt][0]*inv0, Or[nt][1]*inv0);
            *(float2*)(out + rB*H_ + h0) = make_float2(Or[nt][2]*inv1, Or[nt][3]*inv1);
            *(float2*)(out + (size_t)M_*H_ + rA*H_ + h0) = make_float2(Oi[nt][0]*inv0, Oi[nt][1]*inv0);
            *(float2*)(out + (size_t)M_*H_ + rB*H_ + h0) = make_float2(Oi[nt][2]*inv1, Oi[nt][3]*inv1);
        }
        __syncthreads();
    }
}

// ---------------------------------------------------------------------------
extern "C" void kernel_launch(void* const* d_in, const int* in_sizes, int n_in,
                              void* d_out, int out_size)
{
    const float* xr  = (const float*)d_in[0];
    const float* xi  = (const float*)d_in[1];
    const float* Wkr = (const float*)d_in[2];
    const float* Wki = (const float*)d_in[3];
    const float* Wqr = (const float*)d_in[4];
    const float* Wqi = (const float*)d_in[5];
    const float* Wvr = (const float*)d_in[6];
    const float* Wvi = (const float*)d_in[7];

    cudaFuncSetAttribute(proj_kernel,
        cudaFuncAttributeMaxDynamicSharedMemorySize, PJ_U32*4);
    cudaFuncSetAttribute(attn_kernel,
        cudaFuncAttributeMaxDynamicSharedMemorySize, AT_BYTES);

    proj_kernel<<<(M_/128)*3, 512, PJ_U32*4>>>(xr, xi, Wkr, Wki, Wqr, Wqi, Wvr, Wvi);

    dim3 ag(T_/128, B_);
    attn_kernel<<<ag, 512, AT_BYTES>>>((float*)d_out);
}